// round 1
// baseline (speedup 1.0000x reference)
#include <cuda_runtime.h>
#include <math.h>

// Problem constants (match reference)
#define B_   32
#define C_   256
#define CR_  64          // C/R
#define HW_  12544       // 112*112
#define HW4_ 3136        // HW/4
#define NCH  (B_*C_)     // 8192 channels total

// Scratch (no allocation allowed in kernel_launch)
__device__ float g_gap[NCH];
__device__ float g_gate[NCH];

// ---------------------------------------------------------------------------
// Kernel 1: global average pool. One CTA per (b,c) channel.
// ---------------------------------------------------------------------------
__global__ __launch_bounds__(256) void gap_kernel(const float* __restrict__ x) {
    const int bc = blockIdx.x;
    const float4* __restrict__ p =
        reinterpret_cast<const float4*>(x + (size_t)bc * HW_);

    float sum = 0.0f;
    #pragma unroll 4
    for (int i = threadIdx.x; i < HW4_; i += 256) {
        float4 v = p[i];
        sum += (v.x + v.y) + (v.z + v.w);
    }
    // warp reduce
    #pragma unroll
    for (int o = 16; o > 0; o >>= 1)
        sum += __shfl_xor_sync(0xFFFFFFFFu, sum, o);

    __shared__ float s[8];
    if ((threadIdx.x & 31) == 0) s[threadIdx.x >> 5] = sum;
    __syncthreads();
    if (threadIdx.x < 8) {
        sum = s[threadIdx.x];
        #pragma unroll
        for (int o = 4; o > 0; o >>= 1)
            sum += __shfl_xor_sync(0xFFu, sum, o);
        if (threadIdx.x == 0)
            g_gap[bc] = sum * (1.0f / (float)HW_);
    }
}

// ---------------------------------------------------------------------------
// Kernel 2: tiny 2-layer MLP + sigmoid gate. One CTA per batch sample.
// ---------------------------------------------------------------------------
__global__ __launch_bounds__(256) void se_fc_kernel(
    const float* __restrict__ w1, const float* __restrict__ b1,
    const float* __restrict__ w2, const float* __restrict__ b2) {
    const int b = blockIdx.x;
    __shared__ float gap_s[C_];
    __shared__ float h_s[CR_];

    gap_s[threadIdx.x] = g_gap[b * C_ + threadIdx.x];
    __syncthreads();

    if (threadIdx.x < CR_) {
        float acc = b1[threadIdx.x];
        const float* __restrict__ w = w1 + threadIdx.x * C_;
        #pragma unroll 8
        for (int c = 0; c < C_; ++c) acc = fmaf(gap_s[c], w[c], acc);
        h_s[threadIdx.x] = fmaxf(acc, 0.0f);
    }
    __syncthreads();

    float acc = b2[threadIdx.x];
    const float* __restrict__ w = w2 + threadIdx.x * CR_;
    #pragma unroll 8
    for (int o = 0; o < CR_; ++o) acc = fmaf(h_s[o], w[o], acc);
    g_gate[b * C_ + threadIdx.x] = 1.0f / (1.0f + __expf(-acc));
}

// ---------------------------------------------------------------------------
// Kernel 3: out = x * gate[bc]. One CTA per channel, float4 streaming.
// ---------------------------------------------------------------------------
__global__ __launch_bounds__(256) void scale_kernel(
    const float* __restrict__ x, float* __restrict__ out) {
    const int bc = blockIdx.x;
    const float g = g_gate[bc];
    const float4* __restrict__ xp =
        reinterpret_cast<const float4*>(x + (size_t)bc * HW_);
    float4* __restrict__ op =
        reinterpret_cast<float4*>(out + (size_t)bc * HW_);

    #pragma unroll 4
    for (int i = threadIdx.x; i < HW4_; i += 256) {
        float4 v = xp[i];
        v.x *= g; v.y *= g; v.z *= g; v.w *= g;
        op[i] = v;
    }
}

// ---------------------------------------------------------------------------
// Launch
// ---------------------------------------------------------------------------
extern "C" void kernel_launch(void* const* d_in, const int* in_sizes, int n_in,
                              void* d_out, int out_size) {
    const float* x  = (const float*)d_in[0];
    const float* w1 = (const float*)d_in[1];
    const float* b1 = (const float*)d_in[2];
    const float* w2 = (const float*)d_in[3];
    const float* b2 = (const float*)d_in[4];
    float* out = (float*)d_out;

    gap_kernel<<<NCH, 256>>>(x);
    se_fc_kernel<<<B_, 256>>>(w1, b1, w2, b2);
    scale_kernel<<<NCH, 256>>>(x, out);
}

// round 2
// speedup vs baseline: 1.0162x; 1.0162x over previous
#include <cuda_runtime.h>
#include <math.h>

// Problem constants (match reference)
#define B_   32
#define C_   256
#define CR_  64          // C/R
#define HW_  12544       // 112*112
#define HW4_ 3136        // HW/4 (float4 count per channel)
#define NFULL 12         // 3136 = 12*256 + 64
#define NTAIL 64
#define NCH  (B_*C_)     // 8192 channels total

// Scratch (no allocation allowed in kernel_launch)
__device__ float g_gap[NCH];
__device__ float g_gate[NCH];

// ---------------------------------------------------------------------------
// Kernel 1: global average pool. One CTA per (b,c) channel.
// Batched streaming loads: each thread issues 12 (or 13) independent float4
// loads before reducing, to maximize MLP. __ldcs = evict-first (no reuse).
// ---------------------------------------------------------------------------
__global__ __launch_bounds__(256) void gap_kernel(const float* __restrict__ x) {
    const int bc = blockIdx.x;
    const int t  = threadIdx.x;
    const float4* __restrict__ p =
        reinterpret_cast<const float4*>(x + (size_t)bc * HW_);

    float4 v[NFULL];
    #pragma unroll
    for (int k = 0; k < NFULL; ++k)
        v[k] = __ldcs(p + t + k * 256);

    float4 vt;
    if (t < NTAIL) vt = __ldcs(p + t + NFULL * 256);

    float sum = 0.0f;
    #pragma unroll
    for (int k = 0; k < NFULL; ++k)
        sum += (v[k].x + v[k].y) + (v[k].z + v[k].w);
    if (t < NTAIL)
        sum += (vt.x + vt.y) + (vt.z + vt.w);

    // warp reduce
    #pragma unroll
    for (int o = 16; o > 0; o >>= 1)
        sum += __shfl_xor_sync(0xFFFFFFFFu, sum, o);

    __shared__ float s[8];
    if ((t & 31) == 0) s[t >> 5] = sum;
    __syncthreads();
    if (t < 8) {
        sum = s[t];
        #pragma unroll
        for (int o = 4; o > 0; o >>= 1)
            sum += __shfl_xor_sync(0xFFu, sum, o);
        if (t == 0)
            g_gap[bc] = sum * (1.0f / (float)HW_);
    }
}

// ---------------------------------------------------------------------------
// Kernel 2: tiny 2-layer MLP + sigmoid gate. One CTA per batch sample.
// ---------------------------------------------------------------------------
__global__ __launch_bounds__(256) void se_fc_kernel(
    const float* __restrict__ w1, const float* __restrict__ b1,
    const float* __restrict__ w2, const float* __restrict__ b2) {
    const int b = blockIdx.x;
    __shared__ float gap_s[C_];
    __shared__ float h_s[CR_];

    gap_s[threadIdx.x] = g_gap[b * C_ + threadIdx.x];
    __syncthreads();

    if (threadIdx.x < CR_) {
        float acc = b1[threadIdx.x];
        const float* __restrict__ w = w1 + threadIdx.x * C_;
        #pragma unroll 8
        for (int c = 0; c < C_; ++c) acc = fmaf(gap_s[c], w[c], acc);
        h_s[threadIdx.x] = fmaxf(acc, 0.0f);
    }
    __syncthreads();

    float acc = b2[threadIdx.x];
    const float* __restrict__ w = w2 + threadIdx.x * CR_;
    #pragma unroll 8
    for (int o = 0; o < CR_; ++o) acc = fmaf(h_s[o], w[o], acc);
    g_gate[b * C_ + threadIdx.x] = 1.0f / (1.0f + __expf(-acc));
}

// ---------------------------------------------------------------------------
// Kernel 3: out = x * gate[bc]. One CTA per channel.
// Decoupled load burst -> store burst, streaming hints on both sides.
// ---------------------------------------------------------------------------
__global__ __launch_bounds__(256) void scale_kernel(
    const float* __restrict__ x, float* __restrict__ out) {
    const int bc = blockIdx.x;
    const int t  = threadIdx.x;
    const float g = g_gate[bc];
    const float4* __restrict__ xp =
        reinterpret_cast<const float4*>(x + (size_t)bc * HW_);
    float4* __restrict__ op =
        reinterpret_cast<float4*>(out + (size_t)bc * HW_);

    float4 v[NFULL];
    #pragma unroll
    for (int k = 0; k < NFULL; ++k)
        v[k] = __ldcs(xp + t + k * 256);

    float4 vt;
    if (t < NTAIL) vt = __ldcs(xp + t + NFULL * 256);

    #pragma unroll
    for (int k = 0; k < NFULL; ++k) {
        v[k].x *= g; v[k].y *= g; v[k].z *= g; v[k].w *= g;
        __stcs(op + t + k * 256, v[k]);
    }
    if (t < NTAIL) {
        vt.x *= g; vt.y *= g; vt.z *= g; vt.w *= g;
        __stcs(op + t + NFULL * 256, vt);
    }
}

// ---------------------------------------------------------------------------
// Launch
// ---------------------------------------------------------------------------
extern "C" void kernel_launch(void* const* d_in, const int* in_sizes, int n_in,
                              void* d_out, int out_size) {
    const float* x  = (const float*)d_in[0];
    const float* w1 = (const float*)d_in[1];
    const float* b1 = (const float*)d_in[2];
    const float* w2 = (const float*)d_in[3];
    const float* b2 = (const float*)d_in[4];
    float* out = (float*)d_out;

    gap_kernel<<<NCH, 256>>>(x);
    se_fc_kernel<<<B_, 256>>>(w1, b1, w2, b2);
    scale_kernel<<<NCH, 256>>>(x, out);
}

// round 4
// speedup vs baseline: 1.0681x; 1.0511x over previous
#include <cuda_runtime.h>
#include <math.h>

// Problem constants (match reference)
#define B_    32
#define C_    256
#define CR_   64          // C/R
#define HW_   12544       // 112*112
#define HW4_  3136        // HW/4 (float4 count per channel)
#define NFULL 12          // 3136 = 12*256 + 64
#define NTAIL 64
#define HW8_  1568        // HW/8 (float8 count per channel)
#define NFULL8 6          // 1568 = 6*256 + 32
#define NTAIL8 32
#define NCH   (B_*C_)     // 8192 channels total
#define KEEP  2048        // tail channels pinned in L2 between pass 1 and 2 (~103 MB)

// Scratch (no allocation allowed in kernel_launch)
__device__ float g_gap[NCH];
__device__ float g_gate[NCH];

struct F8 { float4 a, b; };

// 32-byte L2 evict-last load (sm_103 requires v8.b32 width with this modifier).
__device__ __forceinline__ F8 ld_evict_last8(const float* p) {
    unsigned r0,r1,r2,r3,r4,r5,r6,r7;
    asm("ld.global.L2::evict_last.v8.b32 {%0,%1,%2,%3,%4,%5,%6,%7}, [%8];"
        : "=r"(r0),"=r"(r1),"=r"(r2),"=r"(r3),
          "=r"(r4),"=r"(r5),"=r"(r6),"=r"(r7) : "l"(p));
    F8 v;
    v.a.x = __uint_as_float(r0); v.a.y = __uint_as_float(r1);
    v.a.z = __uint_as_float(r2); v.a.w = __uint_as_float(r3);
    v.b.x = __uint_as_float(r4); v.b.y = __uint_as_float(r5);
    v.b.z = __uint_as_float(r6); v.b.w = __uint_as_float(r7);
    return v;
}

// ---------------------------------------------------------------------------
// Kernel 1: global average pool. One CTA per (b,c) channel.
// Early channels stream (evict-first); last KEEP channels pinned (evict-last).
// ---------------------------------------------------------------------------
__global__ __launch_bounds__(256) void gap_kernel(const float* __restrict__ x) {
    const int bc = blockIdx.x;
    const int t  = threadIdx.x;
    const float* __restrict__ base = x + (size_t)bc * HW_;
    float sum = 0.0f;

    if (bc >= NCH - KEEP) {
        // pinned path: 32B loads with L2::evict_last
        F8 v[NFULL8];
        #pragma unroll
        for (int k = 0; k < NFULL8; ++k)
            v[k] = ld_evict_last8(base + (t + k * 256) * 8);
        F8 vt;
        if (t < NTAIL8) vt = ld_evict_last8(base + (t + NFULL8 * 256) * 8);

        #pragma unroll
        for (int k = 0; k < NFULL8; ++k)
            sum += ((v[k].a.x + v[k].a.y) + (v[k].a.z + v[k].a.w))
                 + ((v[k].b.x + v[k].b.y) + (v[k].b.z + v[k].b.w));
        if (t < NTAIL8)
            sum += ((vt.a.x + vt.a.y) + (vt.a.z + vt.a.w))
                 + ((vt.b.x + vt.b.y) + (vt.b.z + vt.b.w));
    } else {
        // streaming path: float4 evict-first
        const float4* __restrict__ p = reinterpret_cast<const float4*>(base);
        float4 v[NFULL];
        #pragma unroll
        for (int k = 0; k < NFULL; ++k) v[k] = __ldcs(p + t + k * 256);
        float4 vt;
        if (t < NTAIL) vt = __ldcs(p + t + NFULL * 256);

        #pragma unroll
        for (int k = 0; k < NFULL; ++k)
            sum += (v[k].x + v[k].y) + (v[k].z + v[k].w);
        if (t < NTAIL)
            sum += (vt.x + vt.y) + (vt.z + vt.w);
    }

    // warp reduce
    #pragma unroll
    for (int o = 16; o > 0; o >>= 1)
        sum += __shfl_xor_sync(0xFFFFFFFFu, sum, o);

    __shared__ float s[8];
    if ((t & 31) == 0) s[t >> 5] = sum;
    __syncthreads();
    if (t < 8) {
        sum = s[t];
        #pragma unroll
        for (int o = 4; o > 0; o >>= 1)
            sum += __shfl_xor_sync(0xFFu, sum, o);
        if (t == 0)
            g_gap[bc] = sum * (1.0f / (float)HW_);
    }
}

// ---------------------------------------------------------------------------
// Kernel 2: tiny 2-layer MLP + sigmoid gate. One CTA per batch sample.
// ---------------------------------------------------------------------------
__global__ __launch_bounds__(256) void se_fc_kernel(
    const float* __restrict__ w1, const float* __restrict__ b1,
    const float* __restrict__ w2, const float* __restrict__ b2) {
    const int b = blockIdx.x;
    __shared__ float gap_s[C_];
    __shared__ float h_s[CR_];

    gap_s[threadIdx.x] = g_gap[b * C_ + threadIdx.x];
    __syncthreads();

    if (threadIdx.x < CR_) {
        float acc = b1[threadIdx.x];
        const float* __restrict__ w = w1 + threadIdx.x * C_;
        #pragma unroll 8
        for (int c = 0; c < C_; ++c) acc = fmaf(gap_s[c], w[c], acc);
        h_s[threadIdx.x] = fmaxf(acc, 0.0f);
    }
    __syncthreads();

    float acc = b2[threadIdx.x];
    const float* __restrict__ w = w2 + threadIdx.x * CR_;
    #pragma unroll 8
    for (int o = 0; o < CR_; ++o) acc = fmaf(h_s[o], w[o], acc);
    g_gate[b * C_ + threadIdx.x] = 1.0f / (1.0f + __expf(-acc));
}

// ---------------------------------------------------------------------------
// Kernel 3: out = x * gate[bc]. Reverse channel order so the L2-pinned tail
// from pass 1 is consumed first. Reads evict-first (hit-and-release).
// ---------------------------------------------------------------------------
__global__ __launch_bounds__(256) void scale_kernel(
    const float* __restrict__ x, float* __restrict__ out) {
    const int bc = NCH - 1 - blockIdx.x;     // reverse order
    const int t  = threadIdx.x;
    const float g = g_gate[bc];
    const float4* __restrict__ xp =
        reinterpret_cast<const float4*>(x + (size_t)bc * HW_);
    float4* __restrict__ op =
        reinterpret_cast<float4*>(out + (size_t)bc * HW_);

    float4 v[NFULL];
    #pragma unroll
    for (int k = 0; k < NFULL; ++k)
        v[k] = __ldcs(xp + t + k * 256);

    float4 vt;
    if (t < NTAIL) vt = __ldcs(xp + t + NFULL * 256);

    #pragma unroll
    for (int k = 0; k < NFULL; ++k) {
        v[k].x *= g; v[k].y *= g; v[k].z *= g; v[k].w *= g;
        __stcs(op + t + k * 256, v[k]);
    }
    if (t < NTAIL) {
        vt.x *= g; vt.y *= g; vt.z *= g; vt.w *= g;
        __stcs(op + t + NFULL * 256, vt);
    }
}

// ---------------------------------------------------------------------------
// Launch
// ---------------------------------------------------------------------------
extern "C" void kernel_launch(void* const* d_in, const int* in_sizes, int n_in,
                              void* d_out, int out_size) {
    const float* x  = (const float*)d_in[0];
    const float* w1 = (const float*)d_in[1];
    const float* b1 = (const float*)d_in[2];
    const float* w2 = (const float*)d_in[3];
    const float* b2 = (const float*)d_in[4];
    float* out = (float*)d_out;

    gap_kernel<<<NCH, 256>>>(x);
    se_fc_kernel<<<B_, 256>>>(w1, b1, w2, b2);
    scale_kernel<<<NCH, 256>>>(x, out);
}